// round 4
// baseline (speedup 1.0000x reference)
#include <cuda_runtime.h>
#include <cstdint>

// Problem shape (fixed by the dataset)
#define NROWS 200000
#define NNZV  2000000
#define DIN   300
#define DOUT  96
#define CAP   64   // Poisson(10) per row; P(count > 64) ~ 1e-30 per row

// Scratch: allocation-free (__device__ globals per harness rules)
__device__ int g_cnt[NROWS];
__device__ unsigned long long g_bins[(size_t)NROWS * CAP];

// Vectorized zero of g_cnt (200000 ints = 50000 int4s).
__global__ void zero_cnt_kernel() {
    int i = blockIdx.x * blockDim.x + threadIdx.x;
    int4* p = reinterpret_cast<int4*>(g_cnt);
    if (i < NROWS / 4) p[i] = make_int4(0, 0, 0, 0);
}

// One thread per nonzero: bin (col, val) into its row's slot list.
// NOTE: jax silently demotes int64->int32 (x64 disabled), so indices are i32.
__global__ void __launch_bounds__(256) scatter_kernel(
        const float* __restrict__ val,
        const int* __restrict__ row,
        const int* __restrict__ col) {
    int k = blockIdx.x * blockDim.x + threadIdx.x;
    if (k >= NNZV) return;
    int r = row[k];
    int c = col[k];
    if ((unsigned)r >= NROWS || (unsigned)c >= DIN) return;  // defensive
    float v = val[k];
    int p = atomicAdd(&g_cnt[r], 1);
    if (p < CAP) {
        unsigned long long e = ((unsigned long long)(unsigned)c << 32)
                             | (unsigned long long)__float_as_uint(v);
        g_bins[(size_t)r * CAP + p] = e;
    }
}

// One warp per output row: gather-reduce its nnz, apply bias/relu/mask,
// single coalesced write. Lane L owns output cols {L, L+32, L+64}.
__global__ void __launch_bounds__(256) compute_kernel(
        const float* __restrict__ W,     // [300, 96]
        const float* __restrict__ b,     // [96]
        const float* __restrict__ mask,  // [NROWS]
        float* __restrict__ out) {       // [NROWS, 96]
    int warp = (blockIdx.x * blockDim.x + threadIdx.x) >> 5;
    int lane = threadIdx.x & 31;
    if (warp >= NROWS) return;
    int row = warp;

    int cnt = g_cnt[row];
    if (cnt > CAP) cnt = CAP;
    const unsigned long long* __restrict__ bins = g_bins + (size_t)row * CAP;

    float a0 = 0.f, a1 = 0.f, a2 = 0.f;
    for (int base = 0; base < cnt; base += 32) {
        int n = cnt - base;
        if (n > 32) n = 32;
        // Cooperative coalesced load of this row's entries, then broadcast.
        unsigned long long mine = (lane < n) ? bins[base + lane] : 0ull;
        for (int i = 0; i < n; ++i) {
            unsigned long long e = __shfl_sync(0xffffffffu, mine, i);
            float v = __uint_as_float((unsigned)(e & 0xffffffffull));
            int   c = (int)(e >> 32);
            const float* __restrict__ w = W + c * DOUT;
            a0 = fmaf(v, w[lane],      a0);
            a1 = fmaf(v, w[lane + 32], a1);
            a2 = fmaf(v, w[lane + 64], a2);
        }
    }

    float m = mask[row];
    float* o = out + (size_t)row * DOUT;
    o[lane]      = m * fmaxf(a0 + b[lane],      0.f);
    o[lane + 32] = m * fmaxf(a1 + b[lane + 32], 0.f);
    o[lane + 64] = m * fmaxf(a2 + b[lane + 64], 0.f);
}

extern "C" void kernel_launch(void* const* d_in, const int* in_sizes, int n_in,
                              void* d_out, int out_size) {
    // metadata.txt order == setup_inputs dict order:
    // x_values f32[2M], mask f32[200K], W f32[300*96], b f32[96],
    // x_row i32[2M], x_col i32[2M]   (jax demotes int64->int32)
    const float* x_values = (const float*)d_in[0];
    const float* mask     = (const float*)d_in[1];
    const float* W        = (const float*)d_in[2];
    const float* b        = (const float*)d_in[3];
    const int*   x_row    = (const int*)d_in[4];
    const int*   x_col    = (const int*)d_in[5];
    float* out = (float*)d_out;
    (void)in_sizes; (void)n_in; (void)out_size;

    zero_cnt_kernel<<<(NROWS / 4 + 255) / 256, 256>>>();
    scatter_kernel<<<(NNZV + 255) / 256, 256>>>(x_values, x_row, x_col);
    // 200K warps, 8 warps per 256-thread block
    compute_kernel<<<(NROWS + 7) / 8, 256>>>(W, b, mask, out);
}